// round 2
// baseline (speedup 1.0000x reference)
#include <cuda_runtime.h>
#include <cuda_bf16.h>
#include <math.h>

#define NN 100000
#define EE 1600000
#define HH 128
#define GG 128
#define LL 3
#define BN_EPS 1e-5f

// ---------------- scratch (device globals; no allocation) ----------------
__device__ int   g_deg[NN];
__device__ int   g_fill[NN];
__device__ int   g_rowptr[NN + 1];
__device__ int   g_colidx[EE];
__device__ int   g_gstart[GG + 1];
__device__ float g_dinv[NN];
__device__ float g_t[(size_t)NN * HH];   // post-GEMM features
__device__ float g_h[(size_t)NN * HH];   // post-SpMM activations

// ---------------- CSR build ----------------
__global__ void init_kernel() {
    int i = blockIdx.x * blockDim.x + threadIdx.x;
    if (i < NN) { g_deg[i] = 1; g_fill[i] = 0; }   // self-loop counts 1
}

__global__ void count_kernel(const int* __restrict__ dst) {
    int e = blockIdx.x * blockDim.x + threadIdx.x;
    if (e < EE) atomicAdd(&g_deg[dst[e]], 1);
}

__global__ void dinv_kernel() {
    int i = blockIdx.x * blockDim.x + threadIdx.x;
    if (i < NN) g_dinv[i] = rsqrtf((float)g_deg[i]);
}

__device__ __forceinline__ int warp_incl_scan(int v, unsigned lane) {
#pragma unroll
    for (int o = 1; o < 32; o <<= 1) {
        int t = __shfl_up_sync(0xffffffffu, v, o);
        if (lane >= o) v += t;
    }
    return v;
}

// exclusive prefix sum of (deg-1) -> rowptr ; single block of 1024 threads
__global__ void scan_kernel() {
    __shared__ int wsum[32];
    __shared__ int s_carry;
    int tid = threadIdx.x;
    unsigned lane = tid & 31;
    int wid = tid >> 5;
    if (tid == 0) s_carry = 0;
    for (int base = 0; base < NN; base += 1024) {
        __syncthreads();
        int carry = s_carry;
        int i = base + tid;
        int v = (i < NN) ? (g_deg[i] - 1) : 0;
        int incl = warp_incl_scan(v, lane);
        if (lane == 31) wsum[wid] = incl;
        __syncthreads();
        if (wid == 0) {
            int w = wsum[lane];
            w = warp_incl_scan(w, lane);
            wsum[lane] = w;
        }
        __syncthreads();
        int off = carry + (wid > 0 ? wsum[wid - 1] : 0);
        if (i < NN) g_rowptr[i] = off + incl - v;
        int total = wsum[31];
        __syncthreads();
        if (tid == 0) s_carry = carry + total;
    }
    __syncthreads();
    if (tid == 0) g_rowptr[NN] = s_carry;
}

__global__ void scatter_kernel(const int* __restrict__ src, const int* __restrict__ dst) {
    int e = blockIdx.x * blockDim.x + threadIdx.x;
    if (e < EE) {
        int d = dst[e];
        int p = g_rowptr[d] + atomicAdd(&g_fill[d], 1);
        g_colidx[p] = src[e];
    }
}

__global__ void bounds_kernel(const int* __restrict__ batch) {
    int g = blockIdx.x * blockDim.x + threadIdx.x;
    if (g > GG) return;
    int lo = 0, hi = NN;
    while (lo < hi) {               // first index with batch[i] >= g
        int m = (lo + hi) >> 1;
        if (batch[m] < g) lo = m + 1; else hi = m;
    }
    g_gstart[g] = lo;
}

// ---------------- SGEMM: C[n,128] = A[n,128] @ W[128,128] ----------------
// 128x128 block tile, 256 threads, 8x8 per thread, double-buffered smem.
__global__ void __launch_bounds__(256, 2)
gemm_kernel(const float* __restrict__ A, const float* __restrict__ W,
            float* __restrict__ C, int n) {
    __shared__ float As[2][8][132];
    __shared__ float Bs[2][8][132];

    int tid = threadIdx.x;
    int tx = tid & 15;        // col group 0..15
    int ty = tid >> 4;        // row group 0..15
    int r0 = blockIdx.x * 128;

    int arow = tid >> 1;              // 0..127
    int akq  = (tid & 1) * 4;         // 0 or 4
    int bk   = tid >> 5;              // 0..7
    int bcol = (tid & 31) * 4;        // 0..124

    bool arow_ok = (r0 + arow) < n;
    const float* Ap = A + (size_t)(r0 + arow) * HH + akq;

    float acc[8][8];
#pragma unroll
    for (int i = 0; i < 8; i++)
#pragma unroll
        for (int j = 0; j < 8; j++) acc[i][j] = 0.f;

    // preload step 0
    float4 a4 = arow_ok ? *(const float4*)(Ap) : make_float4(0, 0, 0, 0);
    float4 b4 = *(const float4*)(W + bk * HH + bcol);
    As[0][akq + 0][arow] = a4.x;
    As[0][akq + 1][arow] = a4.y;
    As[0][akq + 2][arow] = a4.z;
    As[0][akq + 3][arow] = a4.w;
    *(float4*)&Bs[0][bk][bcol] = b4;
    __syncthreads();

#pragma unroll 1
    for (int step = 0; step < 16; ++step) {
        int buf = step & 1;
        if (step < 15) {
            a4 = arow_ok ? *(const float4*)(Ap + (step + 1) * 8) : make_float4(0, 0, 0, 0);
            b4 = *(const float4*)(W + ((step + 1) * 8 + bk) * HH + bcol);
        }
#pragma unroll
        for (int k = 0; k < 8; k++) {
            float a[8], b[8];
            *(float4*)&a[0] = *(float4*)&As[buf][k][ty * 4];
            *(float4*)&a[4] = *(float4*)&As[buf][k][64 + ty * 4];
            *(float4*)&b[0] = *(float4*)&Bs[buf][k][tx * 4];
            *(float4*)&b[4] = *(float4*)&Bs[buf][k][64 + tx * 4];
#pragma unroll
            for (int i = 0; i < 8; i++)
#pragma unroll
                for (int j = 0; j < 8; j++) acc[i][j] = fmaf(a[i], b[j], acc[i][j]);
        }
        if (step < 15) {
            __syncthreads();
            int nbuf = buf ^ 1;
            As[nbuf][akq + 0][arow] = a4.x;
            As[nbuf][akq + 1][arow] = a4.y;
            As[nbuf][akq + 2][arow] = a4.z;
            As[nbuf][akq + 3][arow] = a4.w;
            *(float4*)&Bs[nbuf][bk][bcol] = b4;
            __syncthreads();
        }
    }

#pragma unroll
    for (int ri = 0; ri < 2; ri++)
#pragma unroll
        for (int i = 0; i < 4; i++) {
            int r = r0 + ri * 64 + ty * 4 + i;
            if (r < n) {
                int ai = ri * 4 + i;
                float4 v0 = make_float4(acc[ai][0], acc[ai][1], acc[ai][2], acc[ai][3]);
                float4 v1 = make_float4(acc[ai][4], acc[ai][5], acc[ai][6], acc[ai][7]);
                *(float4*)(C + (size_t)r * HH + tx * 4) = v0;
                *(float4*)(C + (size_t)r * HH + 64 + tx * 4) = v1;
            }
        }
}

// ---------------- SpMM + bias + BN + ReLU (warp per node) ----------------
__global__ void spmm_kernel(const float* __restrict__ bias, const float* __restrict__ gamma,
                            const float* __restrict__ beta, const float* __restrict__ rm,
                            const float* __restrict__ rv) {
    int warp = (blockIdx.x * blockDim.x + threadIdx.x) >> 5;
    if (warp >= NN) return;
    int lane = threadIdx.x & 31;
    int v = warp;
    float dv = g_dinv[v];
    const float4* t4 = (const float4*)g_t;

    float4 x = t4[(size_t)v * 32 + lane];
    float ws = dv * dv;
    float4 acc = make_float4(ws * x.x, ws * x.y, ws * x.z, ws * x.w);

    int j = g_rowptr[v], end = g_rowptr[v + 1];
    for (; j + 3 < end; j += 4) {
        int c0 = g_colidx[j], c1 = g_colidx[j + 1], c2 = g_colidx[j + 2], c3 = g_colidx[j + 3];
        float w0 = g_dinv[c0] * dv, w1 = g_dinv[c1] * dv, w2 = g_dinv[c2] * dv, w3 = g_dinv[c3] * dv;
        float4 x0 = t4[(size_t)c0 * 32 + lane];
        float4 x1 = t4[(size_t)c1 * 32 + lane];
        float4 x2 = t4[(size_t)c2 * 32 + lane];
        float4 x3 = t4[(size_t)c3 * 32 + lane];
        acc.x += w0 * x0.x + w1 * x1.x + w2 * x2.x + w3 * x3.x;
        acc.y += w0 * x0.y + w1 * x1.y + w2 * x2.y + w3 * x3.y;
        acc.z += w0 * x0.z + w1 * x1.z + w2 * x2.z + w3 * x3.z;
        acc.w += w0 * x0.w + w1 * x1.w + w2 * x2.w + w3 * x3.w;
    }
    for (; j < end; ++j) {
        int c = g_colidx[j];
        float w = g_dinv[c] * dv;
        float4 xx = t4[(size_t)c * 32 + lane];
        acc.x += w * xx.x; acc.y += w * xx.y; acc.z += w * xx.z; acc.w += w * xx.w;
    }

    float4 b  = *(const float4*)(bias  + lane * 4);
    float4 gm = *(const float4*)(gamma + lane * 4);
    float4 bt = *(const float4*)(beta  + lane * 4);
    float4 m  = *(const float4*)(rm    + lane * 4);
    float4 vv = *(const float4*)(rv    + lane * 4);

    float s0 = gm.x * rsqrtf(vv.x + BN_EPS);
    float s1 = gm.y * rsqrtf(vv.y + BN_EPS);
    float s2 = gm.z * rsqrtf(vv.z + BN_EPS);
    float s3 = gm.w * rsqrtf(vv.w + BN_EPS);

    float4 o;
    o.x = fmaxf((acc.x + b.x - m.x) * s0 + bt.x, 0.f);
    o.y = fmaxf((acc.y + b.y - m.y) * s1 + bt.y, 0.f);
    o.z = fmaxf((acc.z + b.z - m.z) * s2 + bt.z, 0.f);
    o.w = fmaxf((acc.w + b.w - m.w) * s3 + bt.w, 0.f);
    ((float4*)g_h)[(size_t)v * 32 + lane] = o;
}

// ---------------- pool + LSTM + FC (block per graph) ----------------
__device__ __forceinline__ float sigmoidf_(float x) { return 1.f / (1.f + expf(-x)); }

__global__ void pool_lstm_kernel(const float* __restrict__ W_ih, const float* __restrict__ b_ih,
                                 const float* __restrict__ b_hh, const float* __restrict__ W_fc,
                                 const float* __restrict__ b_fc, float* __restrict__ out) {
    int g = blockIdx.x;
    int j = threadIdx.x;  // 0..127
    __shared__ __align__(16) float p[HH];
    __shared__ __align__(16) float hn[HH];

    int s = g_gstart[g], e = g_gstart[g + 1];
    float sum = 0.f;
    int n = s;
    for (; n + 3 < e; n += 4) {
        sum += g_h[(size_t)n * HH + j] + g_h[(size_t)(n + 1) * HH + j]
             + g_h[(size_t)(n + 2) * HH + j] + g_h[(size_t)(n + 3) * HH + j];
    }
    for (; n < e; ++n) sum += g_h[(size_t)n * HH + j];
    float cnt = (float)((e - s) > 0 ? (e - s) : 1);
    p[j] = sum / cnt;
    __syncthreads();

    float gate[4];
#pragma unroll
    for (int q = 0; q < 4; q++) {
        const float4* wr = (const float4*)(W_ih + (size_t)(q * HH + j) * HH);
        const float4* pp = (const float4*)p;
        float a = 0.f;
#pragma unroll
        for (int k = 0; k < 32; k++) {
            float4 w = wr[k];
            float4 x = pp[k];
            a += w.x * x.x + w.y * x.y + w.z * x.z + w.w * x.w;
        }
        gate[q] = a + b_ih[q * HH + j] + b_hh[q * HH + j];
    }
    float iv = sigmoidf_(gate[0]);
    float gv = tanhf(gate[2]);
    float ov = sigmoidf_(gate[3]);
    float c = iv * gv;
    hn[j] = ov * tanhf(c);
    __syncthreads();

    if (j < 16) {
        const float4* wr = (const float4*)(W_fc + (size_t)j * HH);
        const float4* hh = (const float4*)hn;
        float a = b_fc[j];
#pragma unroll
        for (int k = 0; k < 32; k++) {
            float4 w = wr[k];
            float4 x = hh[k];
            a += w.x * x.x + w.y * x.y + w.z * x.z + w.w * x.w;
        }
        out[g * 16 + j] = a;
    }
}

// ---------------- host-side symbol address helpers (declared BEFORE use) ----------------
static float* get_h_ptr() {
    static float* p = nullptr;
    if (!p) cudaGetSymbolAddress((void**)&p, g_h);
    return p;
}
static float* get_t_ptr() {
    static float* p = nullptr;
    if (!p) cudaGetSymbolAddress((void**)&p, g_t);
    return p;
}

// ---------------- launch ----------------
extern "C" void kernel_launch(void* const* d_in, const int* in_sizes, int n_in,
                              void* d_out, int out_size) {
    const float* x     = (const float*)d_in[0];
    const int*   eidx  = (const int*)d_in[1];      // [2, E] : src row then dst row
    const int*   batch = (const int*)d_in[2];
    const float* Ws    = (const float*)d_in[3];    // [3,128,128]
    const float* bs    = (const float*)d_in[4];    // [3,128]
    const float* gam   = (const float*)d_in[5];
    const float* bet   = (const float*)d_in[6];
    const float* rms   = (const float*)d_in[7];
    const float* rvs   = (const float*)d_in[8];
    const float* W_ih  = (const float*)d_in[9];    // [512,128]
    // d_in[10] = W_hh (unused: h0 = c0 = 0)
    const float* b_ih  = (const float*)d_in[11];
    const float* b_hh  = (const float*)d_in[12];
    const float* W_fc  = (const float*)d_in[13];   // [16,128]
    const float* b_fc  = (const float*)d_in[14];
    float* out = (float*)d_out;

    const int* src = eidx;
    const int* dst = eidx + EE;

    float* h_ptr = get_h_ptr();
    float* t_ptr = get_t_ptr();

    init_kernel<<<(NN + 255) / 256, 256>>>();
    count_kernel<<<(EE + 255) / 256, 256>>>(dst);
    dinv_kernel<<<(NN + 255) / 256, 256>>>();
    scan_kernel<<<1, 1024>>>();
    scatter_kernel<<<(EE + 255) / 256, 256>>>(src, dst);
    bounds_kernel<<<1, 256>>>(batch);

    int gemm_blocks = (NN + 127) / 128;
    int spmm_blocks = (NN * 32 + 255) / 256;
    for (int l = 0; l < LL; l++) {
        const float* A = (l == 0) ? x : h_ptr;
        gemm_kernel<<<gemm_blocks, 256>>>(A, Ws + (size_t)l * HH * HH, t_ptr, NN);
        spmm_kernel<<<spmm_blocks, 256>>>(bs + l * HH, gam + l * HH, bet + l * HH,
                                          rms + l * HH, rvs + l * HH);
    }
    pool_lstm_kernel<<<GG, 128>>>(W_ih, b_ih, b_hh, W_fc, b_fc, out);
}

// round 3
// speedup vs baseline: 1.1014x; 1.1014x over previous
#include <cuda_runtime.h>
#include <cuda_bf16.h>
#include <math.h>

#define NN 100000
#define EE 1600000
#define HH 128
#define GG 128
#define LL 3
#define BN_EPS 1e-5f

#define SCAN_CHUNK 1024
#define SCAN_BLOCKS ((NN + SCAN_CHUNK - 1) / SCAN_CHUNK)   // 98

// ---------------- scratch (device globals; no allocation) ----------------
__device__ int   g_deg[NN];
__device__ int   g_fill[NN];
__device__ int   g_rowptr[NN + 1];
__device__ int   g_colidx[EE];
__device__ int   g_gstart[GG + 1];
__device__ int   g_bsum[SCAN_BLOCKS];
__device__ float g_dinv[NN];
__device__ float g_t[(size_t)NN * HH];   // post-GEMM features
__device__ float g_h[(size_t)NN * HH];   // post-SpMM activations

// ---------------- CSR build ----------------
__global__ void init_kernel() {
    int i = blockIdx.x * blockDim.x + threadIdx.x;
    if (i < NN) { g_deg[i] = 1; g_fill[i] = 0; }   // self-loop counts 1
}

__global__ void count_kernel(const int* __restrict__ dst) {
    int e = blockIdx.x * blockDim.x + threadIdx.x;
    if (e < EE) atomicAdd(&g_deg[dst[e]], 1);
}

__global__ void dinv_kernel() {
    int i = blockIdx.x * blockDim.x + threadIdx.x;
    if (i < NN) g_dinv[i] = rsqrtf((float)g_deg[i]);
}

__device__ __forceinline__ int warp_incl_scan(int v, unsigned lane) {
#pragma unroll
    for (int o = 1; o < 32; o <<= 1) {
        int t = __shfl_up_sync(0xffffffffu, v, o);
        if (lane >= o) v += t;
    }
    return v;
}

// phase 1: per-block reduction of (deg-1)
__global__ void scan_reduce_kernel() {
    __shared__ int wsum[32];
    int tid = threadIdx.x;
    unsigned lane = tid & 31;
    int wid = tid >> 5;
    int i = blockIdx.x * SCAN_CHUNK + tid;
    int v = (i < NN) ? (g_deg[i] - 1) : 0;
#pragma unroll
    for (int o = 16; o > 0; o >>= 1) v += __shfl_down_sync(0xffffffffu, v, o);
    if (lane == 0) wsum[wid] = v;
    __syncthreads();
    if (wid == 0) {
        int w = (lane < 32) ? wsum[lane] : 0;
#pragma unroll
        for (int o = 16; o > 0; o >>= 1) w += __shfl_down_sync(0xffffffffu, w, o);
        if (lane == 0) g_bsum[blockIdx.x] = w;
    }
}

// phase 2: exclusive scan of the 98 block sums (single 128-thread block)
__global__ void scan_spine_kernel() {
    __shared__ int wtot[4];
    int tid = threadIdx.x;              // 0..127
    unsigned lane = tid & 31;
    int wid = tid >> 5;
    int v = (tid < SCAN_BLOCKS) ? g_bsum[tid] : 0;
    int incl = warp_incl_scan(v, lane);
    if (lane == 31) wtot[wid] = incl;
    __syncthreads();
    int off = 0;
    for (int w = 0; w < wid; w++) off += wtot[w];
    if (tid < SCAN_BLOCKS) g_bsum[tid] = off + incl - v;   // exclusive
    if (tid == 127) g_rowptr[NN] = off + incl;             // grand total
}

// phase 3: local exclusive scan + spine offset -> rowptr
__global__ void scan_apply_kernel() {
    __shared__ int wsum[32];
    int tid = threadIdx.x;
    unsigned lane = tid & 31;
    int wid = tid >> 5;
    int i = blockIdx.x * SCAN_CHUNK + tid;
    int v = (i < NN) ? (g_deg[i] - 1) : 0;
    int incl = warp_incl_scan(v, lane);
    if (lane == 31) wsum[wid] = incl;
    __syncthreads();
    int woff = 0;
    for (int w = 0; w < wid; w++) woff += wsum[w];
    if (i < NN) g_rowptr[i] = g_bsum[blockIdx.x] + woff + incl - v;
}

__global__ void scatter_kernel(const int* __restrict__ src, const int* __restrict__ dst) {
    int e = blockIdx.x * blockDim.x + threadIdx.x;
    if (e < EE) {
        int d = dst[e];
        int p = g_rowptr[d] + atomicAdd(&g_fill[d], 1);
        g_colidx[p] = src[e];
    }
}

__global__ void bounds_kernel(const int* __restrict__ batch) {
    int g = blockIdx.x * blockDim.x + threadIdx.x;
    if (g > GG) return;
    int lo = 0, hi = NN;
    while (lo < hi) {               // first index with batch[i] >= g
        int m = (lo + hi) >> 1;
        if (batch[m] < g) lo = m + 1; else hi = m;
    }
    g_gstart[g] = lo;
}

// ---------------- SGEMM: C[n,128] = A[n,128] @ W[128,128] ----------------
// 128x128 block tile, 256 threads, 8x8 per thread, double-buffered smem.
__global__ void __launch_bounds__(256, 2)
gemm_kernel(const float* __restrict__ A, const float* __restrict__ W,
            float* __restrict__ C, int n) {
    __shared__ float As[2][8][132];
    __shared__ float Bs[2][8][132];

    int tid = threadIdx.x;
    int tx = tid & 15;        // col group 0..15
    int ty = tid >> 4;        // row group 0..15
    int r0 = blockIdx.x * 128;

    int arow = tid >> 1;              // 0..127
    int akq  = (tid & 1) * 4;         // 0 or 4
    int bk   = tid >> 5;              // 0..7
    int bcol = (tid & 31) * 4;        // 0..124

    bool arow_ok = (r0 + arow) < n;
    const float* Ap = A + (size_t)(r0 + arow) * HH + akq;

    float acc[8][8];
#pragma unroll
    for (int i = 0; i < 8; i++)
#pragma unroll
        for (int j = 0; j < 8; j++) acc[i][j] = 0.f;

    // preload step 0
    float4 a4 = arow_ok ? *(const float4*)(Ap) : make_float4(0, 0, 0, 0);
    float4 b4 = *(const float4*)(W + bk * HH + bcol);
    As[0][akq + 0][arow] = a4.x;
    As[0][akq + 1][arow] = a4.y;
    As[0][akq + 2][arow] = a4.z;
    As[0][akq + 3][arow] = a4.w;
    *(float4*)&Bs[0][bk][bcol] = b4;
    __syncthreads();

#pragma unroll 1
    for (int step = 0; step < 16; ++step) {
        int buf = step & 1;
        if (step < 15) {
            a4 = arow_ok ? *(const float4*)(Ap + (step + 1) * 8) : make_float4(0, 0, 0, 0);
            b4 = *(const float4*)(W + ((step + 1) * 8 + bk) * HH + bcol);
        }
#pragma unroll
        for (int k = 0; k < 8; k++) {
            float a[8], b[8];
            *(float4*)&a[0] = *(float4*)&As[buf][k][ty * 4];
            *(float4*)&a[4] = *(float4*)&As[buf][k][64 + ty * 4];
            *(float4*)&b[0] = *(float4*)&Bs[buf][k][tx * 4];
            *(float4*)&b[4] = *(float4*)&Bs[buf][k][64 + tx * 4];
#pragma unroll
            for (int i = 0; i < 8; i++)
#pragma unroll
                for (int j = 0; j < 8; j++) acc[i][j] = fmaf(a[i], b[j], acc[i][j]);
        }
        if (step < 15) {
            __syncthreads();
            int nbuf = buf ^ 1;
            As[nbuf][akq + 0][arow] = a4.x;
            As[nbuf][akq + 1][arow] = a4.y;
            As[nbuf][akq + 2][arow] = a4.z;
            As[nbuf][akq + 3][arow] = a4.w;
            *(float4*)&Bs[nbuf][bk][bcol] = b4;
            __syncthreads();
        }
    }

#pragma unroll
    for (int ri = 0; ri < 2; ri++)
#pragma unroll
        for (int i = 0; i < 4; i++) {
            int r = r0 + ri * 64 + ty * 4 + i;
            if (r < n) {
                int ai = ri * 4 + i;
                float4 v0 = make_float4(acc[ai][0], acc[ai][1], acc[ai][2], acc[ai][3]);
                float4 v1 = make_float4(acc[ai][4], acc[ai][5], acc[ai][6], acc[ai][7]);
                *(float4*)(C + (size_t)r * HH + tx * 4) = v0;
                *(float4*)(C + (size_t)r * HH + 64 + tx * 4) = v1;
            }
        }
}

// ---------------- SpMM + bias + BN + ReLU (warp per node) ----------------
__global__ void spmm_kernel(const float* __restrict__ bias, const float* __restrict__ gamma,
                            const float* __restrict__ beta, const float* __restrict__ rm,
                            const float* __restrict__ rv) {
    int warp = (blockIdx.x * blockDim.x + threadIdx.x) >> 5;
    if (warp >= NN) return;
    int lane = threadIdx.x & 31;
    int v = warp;
    float dv = g_dinv[v];
    const float4* t4 = (const float4*)g_t;

    float4 x = t4[(size_t)v * 32 + lane];
    float ws = dv * dv;
    float4 acc = make_float4(ws * x.x, ws * x.y, ws * x.z, ws * x.w);

    int j = g_rowptr[v], end = g_rowptr[v + 1];
    for (; j + 3 < end; j += 4) {
        int c0 = g_colidx[j], c1 = g_colidx[j + 1], c2 = g_colidx[j + 2], c3 = g_colidx[j + 3];
        float w0 = g_dinv[c0] * dv, w1 = g_dinv[c1] * dv, w2 = g_dinv[c2] * dv, w3 = g_dinv[c3] * dv;
        float4 x0 = t4[(size_t)c0 * 32 + lane];
        float4 x1 = t4[(size_t)c1 * 32 + lane];
        float4 x2 = t4[(size_t)c2 * 32 + lane];
        float4 x3 = t4[(size_t)c3 * 32 + lane];
        acc.x += w0 * x0.x + w1 * x1.x + w2 * x2.x + w3 * x3.x;
        acc.y += w0 * x0.y + w1 * x1.y + w2 * x2.y + w3 * x3.y;
        acc.z += w0 * x0.z + w1 * x1.z + w2 * x2.z + w3 * x3.z;
        acc.w += w0 * x0.w + w1 * x1.w + w2 * x2.w + w3 * x3.w;
    }
    for (; j < end; ++j) {
        int c = g_colidx[j];
        float w = g_dinv[c] * dv;
        float4 xx = t4[(size_t)c * 32 + lane];
        acc.x += w * xx.x; acc.y += w * xx.y; acc.z += w * xx.z; acc.w += w * xx.w;
    }

    float4 b  = *(const float4*)(bias  + lane * 4);
    float4 gm = *(const float4*)(gamma + lane * 4);
    float4 bt = *(const float4*)(beta  + lane * 4);
    float4 m  = *(const float4*)(rm    + lane * 4);
    float4 vv = *(const float4*)(rv    + lane * 4);

    float s0 = gm.x * rsqrtf(vv.x + BN_EPS);
    float s1 = gm.y * rsqrtf(vv.y + BN_EPS);
    float s2 = gm.z * rsqrtf(vv.z + BN_EPS);
    float s3 = gm.w * rsqrtf(vv.w + BN_EPS);

    float4 o;
    o.x = fmaxf((acc.x + b.x - m.x) * s0 + bt.x, 0.f);
    o.y = fmaxf((acc.y + b.y - m.y) * s1 + bt.y, 0.f);
    o.z = fmaxf((acc.z + b.z - m.z) * s2 + bt.z, 0.f);
    o.w = fmaxf((acc.w + b.w - m.w) * s3 + bt.w, 0.f);
    ((float4*)g_h)[(size_t)v * 32 + lane] = o;
}

// ---------------- pool + LSTM + FC (block per graph) ----------------
__device__ __forceinline__ float sigmoidf_(float x) { return 1.f / (1.f + expf(-x)); }

__global__ void pool_lstm_kernel(const float* __restrict__ W_ih, const float* __restrict__ b_ih,
                                 const float* __restrict__ b_hh, const float* __restrict__ W_fc,
                                 const float* __restrict__ b_fc, float* __restrict__ out) {
    int g = blockIdx.x;
    int j = threadIdx.x;  // 0..127
    __shared__ __align__(16) float p[HH];
    __shared__ __align__(16) float hn[HH];

    int s = g_gstart[g], e = g_gstart[g + 1];
    float sum = 0.f;
    int n = s;
    for (; n + 3 < e; n += 4) {
        sum += g_h[(size_t)n * HH + j] + g_h[(size_t)(n + 1) * HH + j]
             + g_h[(size_t)(n + 2) * HH + j] + g_h[(size_t)(n + 3) * HH + j];
    }
    for (; n < e; ++n) sum += g_h[(size_t)n * HH + j];
    float cnt = (float)((e - s) > 0 ? (e - s) : 1);
    p[j] = sum / cnt;
    __syncthreads();

    float gate[4];
#pragma unroll
    for (int q = 0; q < 4; q++) {
        const float4* wr = (const float4*)(W_ih + (size_t)(q * HH + j) * HH);
        const float4* pp = (const float4*)p;
        float a = 0.f;
#pragma unroll
        for (int k = 0; k < 32; k++) {
            float4 w = wr[k];
            float4 x = pp[k];
            a += w.x * x.x + w.y * x.y + w.z * x.z + w.w * x.w;
        }
        gate[q] = a + b_ih[q * HH + j] + b_hh[q * HH + j];
    }
    float iv = sigmoidf_(gate[0]);
    float gv = tanhf(gate[2]);
    float ov = sigmoidf_(gate[3]);
    float c = iv * gv;
    hn[j] = ov * tanhf(c);
    __syncthreads();

    if (j < 16) {
        const float4* wr = (const float4*)(W_fc + (size_t)j * HH);
        const float4* hh = (const float4*)hn;
        float a = b_fc[j];
#pragma unroll
        for (int k = 0; k < 32; k++) {
            float4 w = wr[k];
            float4 x = hh[k];
            a += w.x * x.x + w.y * x.y + w.z * x.z + w.w * x.w;
        }
        out[g * 16 + j] = a;
    }
}

// ---------------- host-side symbol address helpers ----------------
static float* get_h_ptr() {
    static float* p = nullptr;
    if (!p) cudaGetSymbolAddress((void**)&p, g_h);
    return p;
}
static float* get_t_ptr() {
    static float* p = nullptr;
    if (!p) cudaGetSymbolAddress((void**)&p, g_t);
    return p;
}

// ---------------- launch ----------------
extern "C" void kernel_launch(void* const* d_in, const int* in_sizes, int n_in,
                              void* d_out, int out_size) {
    const float* x     = (const float*)d_in[0];
    const int*   eidx  = (const int*)d_in[1];      // [2, E] : src row then dst row
    const int*   batch = (const int*)d_in[2];
    const float* Ws    = (const float*)d_in[3];    // [3,128,128]
    const float* bs    = (const float*)d_in[4];    // [3,128]
    const float* gam   = (const float*)d_in[5];
    const float* bet   = (const float*)d_in[6];
    const float* rms   = (const float*)d_in[7];
    const float* rvs   = (const float*)d_in[8];
    const float* W_ih  = (const float*)d_in[9];    // [512,128]
    // d_in[10] = W_hh (unused: h0 = c0 = 0)
    const float* b_ih  = (const float*)d_in[11];
    const float* b_hh  = (const float*)d_in[12];
    const float* W_fc  = (const float*)d_in[13];   // [16,128]
    const float* b_fc  = (const float*)d_in[14];
    float* out = (float*)d_out;

    const int* src = eidx;
    const int* dst = eidx + EE;

    float* h_ptr = get_h_ptr();
    float* t_ptr = get_t_ptr();

    init_kernel<<<(NN + 255) / 256, 256>>>();
    count_kernel<<<(EE + 255) / 256, 256>>>(dst);
    dinv_kernel<<<(NN + 255) / 256, 256>>>();
    scan_reduce_kernel<<<SCAN_BLOCKS, SCAN_CHUNK>>>();
    scan_spine_kernel<<<1, 128>>>();
    scan_apply_kernel<<<SCAN_BLOCKS, SCAN_CHUNK>>>();
    scatter_kernel<<<(EE + 255) / 256, 256>>>(src, dst);
    bounds_kernel<<<1, 256>>>(batch);

    int gemm_blocks = (NN + 127) / 128;
    int spmm_blocks = (NN * 32 + 255) / 256;
    for (int l = 0; l < LL; l++) {
        const float* A = (l == 0) ? x : h_ptr;
        gemm_kernel<<<gemm_blocks, 256>>>(A, Ws + (size_t)l * HH * HH, t_ptr, NN);
        spmm_kernel<<<spmm_blocks, 256>>>(bs + l * HH, gam + l * HH, bet + l * HH,
                                          rms + l * HH, rvs + l * HH);
    }
    pool_lstm_kernel<<<GG, 128>>>(W_ih, b_ih, b_hh, W_fc, b_fc, out);
}

// round 4
// speedup vs baseline: 1.2364x; 1.1225x over previous
#include <cuda_runtime.h>
#include <cuda_fp16.h>
#include <math.h>

#define NN 100000
#define EE 1600000
#define HH 128
#define GG 128
#define LL 3
#define BN_EPS 1e-5f

#define SCAN_CHUNK 1024
#define SCAN_BLOCKS ((NN + SCAN_CHUNK - 1) / SCAN_CHUNK)   // 98

// ---------------- scratch (device globals; no allocation) ----------------
__device__ int   g_deg[NN];
__device__ int   g_fill[NN];
__device__ int   g_rowptr[NN + 1];
__device__ int   g_colidx[EE];
__device__ int   g_gstart[GG + 1];
__device__ int   g_bsum[SCAN_BLOCKS];
__device__ float g_dinv[NN];
__device__ __half2 g_t[(size_t)NN * HH / 2];   // post-GEMM features (fp16)
__device__ float g_h[(size_t)NN * HH];         // post-SpMM activations (fp32)

// ---------------- CSR build ----------------
__global__ void init_kernel() {
    int i = blockIdx.x * blockDim.x + threadIdx.x;
    if (i < NN) { g_deg[i] = 1; g_fill[i] = 0; }   // self-loop counts 1
}

__global__ void count_kernel(const int* __restrict__ dst) {
    int e = blockIdx.x * blockDim.x + threadIdx.x;
    if (e < EE) atomicAdd(&g_deg[dst[e]], 1);
}

__global__ void dinv_kernel() {
    int i = blockIdx.x * blockDim.x + threadIdx.x;
    if (i < NN) g_dinv[i] = rsqrtf((float)g_deg[i]);
}

__device__ __forceinline__ int warp_incl_scan(int v, unsigned lane) {
#pragma unroll
    for (int o = 1; o < 32; o <<= 1) {
        int t = __shfl_up_sync(0xffffffffu, v, o);
        if (lane >= o) v += t;
    }
    return v;
}

// phase 1: per-block reduction of (deg-1)
__global__ void scan_reduce_kernel() {
    __shared__ int wsum[32];
    int tid = threadIdx.x;
    unsigned lane = tid & 31;
    int wid = tid >> 5;
    int i = blockIdx.x * SCAN_CHUNK + tid;
    int v = (i < NN) ? (g_deg[i] - 1) : 0;
#pragma unroll
    for (int o = 16; o > 0; o >>= 1) v += __shfl_down_sync(0xffffffffu, v, o);
    if (lane == 0) wsum[wid] = v;
    __syncthreads();
    if (wid == 0) {
        int w = wsum[lane];
#pragma unroll
        for (int o = 16; o > 0; o >>= 1) w += __shfl_down_sync(0xffffffffu, w, o);
        if (lane == 0) g_bsum[blockIdx.x] = w;
    }
}

// phase 2: exclusive scan of the 98 block sums (single 128-thread block)
__global__ void scan_spine_kernel() {
    __shared__ int wtot[4];
    int tid = threadIdx.x;              // 0..127
    unsigned lane = tid & 31;
    int wid = tid >> 5;
    int v = (tid < SCAN_BLOCKS) ? g_bsum[tid] : 0;
    int incl = warp_incl_scan(v, lane);
    if (lane == 31) wtot[wid] = incl;
    __syncthreads();
    int off = 0;
    for (int w = 0; w < wid; w++) off += wtot[w];
    if (tid < SCAN_BLOCKS) g_bsum[tid] = off + incl - v;   // exclusive
    if (tid == 127) g_rowptr[NN] = off + incl;             // grand total
}

// phase 3: local exclusive scan + spine offset -> rowptr
__global__ void scan_apply_kernel() {
    __shared__ int wsum[32];
    int tid = threadIdx.x;
    unsigned lane = tid & 31;
    int wid = tid >> 5;
    int i = blockIdx.x * SCAN_CHUNK + tid;
    int v = (i < NN) ? (g_deg[i] - 1) : 0;
    int incl = warp_incl_scan(v, lane);
    if (lane == 31) wsum[wid] = incl;
    __syncthreads();
    int woff = 0;
    for (int w = 0; w < wid; w++) woff += wsum[w];
    if (i < NN) g_rowptr[i] = g_bsum[blockIdx.x] + woff + incl - v;
}

__global__ void scatter_kernel(const int* __restrict__ src, const int* __restrict__ dst) {
    int e = blockIdx.x * blockDim.x + threadIdx.x;
    if (e < EE) {
        int d = dst[e];
        int p = g_rowptr[d] + atomicAdd(&g_fill[d], 1);
        g_colidx[p] = src[e];
    }
}

__global__ void bounds_kernel(const int* __restrict__ batch) {
    int g = blockIdx.x * blockDim.x + threadIdx.x;
    if (g > GG) return;
    int lo = 0, hi = NN;
    while (lo < hi) {               // first index with batch[i] >= g
        int m = (lo + hi) >> 1;
        if (batch[m] < g) lo = m + 1; else hi = m;
    }
    g_gstart[g] = lo;
}

// ---------------- SGEMM: C[n,128](fp16) = A[n,128](fp32) @ W[128,128] ----------------
// 128x128 block tile, 256 threads, 8x8 per thread, double-buffered smem.
__global__ void __launch_bounds__(256, 2)
gemm_kernel(const float* __restrict__ A, const float* __restrict__ W,
            __half2* __restrict__ C2, int n) {
    __shared__ float As[2][8][132];
    __shared__ float Bs[2][8][132];

    int tid = threadIdx.x;
    int tx = tid & 15;        // col group 0..15
    int ty = tid >> 4;        // row group 0..15
    int r0 = blockIdx.x * 128;

    int arow = tid >> 1;              // 0..127
    int akq  = (tid & 1) * 4;         // 0 or 4
    int bk   = tid >> 5;              // 0..7
    int bcol = (tid & 31) * 4;        // 0..124

    bool arow_ok = (r0 + arow) < n;
    const float* Ap = A + (size_t)(r0 + arow) * HH + akq;

    float acc[8][8];
#pragma unroll
    for (int i = 0; i < 8; i++)
#pragma unroll
        for (int j = 0; j < 8; j++) acc[i][j] = 0.f;

    // preload step 0
    float4 a4 = arow_ok ? *(const float4*)(Ap) : make_float4(0, 0, 0, 0);
    float4 b4 = *(const float4*)(W + bk * HH + bcol);
    As[0][akq + 0][arow] = a4.x;
    As[0][akq + 1][arow] = a4.y;
    As[0][akq + 2][arow] = a4.z;
    As[0][akq + 3][arow] = a4.w;
    *(float4*)&Bs[0][bk][bcol] = b4;
    __syncthreads();

#pragma unroll 1
    for (int step = 0; step < 16; ++step) {
        int buf = step & 1;
        if (step < 15) {
            a4 = arow_ok ? *(const float4*)(Ap + (step + 1) * 8) : make_float4(0, 0, 0, 0);
            b4 = *(const float4*)(W + ((step + 1) * 8 + bk) * HH + bcol);
        }
#pragma unroll
        for (int k = 0; k < 8; k++) {
            float a[8], b[8];
            *(float4*)&a[0] = *(float4*)&As[buf][k][ty * 4];
            *(float4*)&a[4] = *(float4*)&As[buf][k][64 + ty * 4];
            *(float4*)&b[0] = *(float4*)&Bs[buf][k][tx * 4];
            *(float4*)&b[4] = *(float4*)&Bs[buf][k][64 + tx * 4];
#pragma unroll
            for (int i = 0; i < 8; i++)
#pragma unroll
                for (int j = 0; j < 8; j++) acc[i][j] = fmaf(a[i], b[j], acc[i][j]);
        }
        if (step < 15) {
            __syncthreads();
            int nbuf = buf ^ 1;
            As[nbuf][akq + 0][arow] = a4.x;
            As[nbuf][akq + 1][arow] = a4.y;
            As[nbuf][akq + 2][arow] = a4.z;
            As[nbuf][akq + 3][arow] = a4.w;
            *(float4*)&Bs[nbuf][bk][bcol] = b4;
            __syncthreads();
        }
    }

    // epilogue: convert to fp16 pairs, store 8B per half-row-segment
#pragma unroll
    for (int ri = 0; ri < 2; ri++)
#pragma unroll
        for (int i = 0; i < 4; i++) {
            int r = r0 + ri * 64 + ty * 4 + i;
            if (r < n) {
                int ai = ri * 4 + i;
                __half2 p0 = __floats2half2_rn(acc[ai][0], acc[ai][1]);
                __half2 p1 = __floats2half2_rn(acc[ai][2], acc[ai][3]);
                __half2 p2 = __floats2half2_rn(acc[ai][4], acc[ai][5]);
                __half2 p3 = __floats2half2_rn(acc[ai][6], acc[ai][7]);
                uint2 u0, u1;
                u0.x = *(unsigned*)&p0; u0.y = *(unsigned*)&p1;
                u1.x = *(unsigned*)&p2; u1.y = *(unsigned*)&p3;
                *(uint2*)(C2 + (size_t)r * 64 + tx * 2)      = u0;
                *(uint2*)(C2 + (size_t)r * 64 + 32 + tx * 2) = u1;
            }
        }
}

// ---------------- SpMM + bias + BN + ReLU (warp per node, fp16 gathers) ----------------
__global__ void spmm_kernel(const float* __restrict__ bias, const float* __restrict__ gamma,
                            const float* __restrict__ beta, const float* __restrict__ rm,
                            const float* __restrict__ rv) {
    int warp = (blockIdx.x * blockDim.x + threadIdx.x) >> 5;
    if (warp >= NN) return;
    int lane = threadIdx.x & 31;
    int v = warp;
    float dv = g_dinv[v];
    const uint2* t8 = (const uint2*)g_t;   // 8 bytes = 4 fp16 features

    // self loop: weight dv*dv
    uint2 xs = t8[(size_t)v * 32 + lane];
    float2 f01 = __half22float2(*(__half2*)&xs.x);
    float2 f23 = __half22float2(*(__half2*)&xs.y);
    float ws = dv * dv;
    float4 acc = make_float4(ws * f01.x, ws * f01.y, ws * f23.x, ws * f23.y);

    int j = g_rowptr[v], end = g_rowptr[v + 1];
    for (; j + 3 < end; j += 4) {
        int c0 = g_colidx[j], c1 = g_colidx[j + 1], c2 = g_colidx[j + 2], c3 = g_colidx[j + 3];
        float w0 = g_dinv[c0] * dv, w1 = g_dinv[c1] * dv, w2 = g_dinv[c2] * dv, w3 = g_dinv[c3] * dv;
        uint2 x0 = t8[(size_t)c0 * 32 + lane];
        uint2 x1 = t8[(size_t)c1 * 32 + lane];
        uint2 x2 = t8[(size_t)c2 * 32 + lane];
        uint2 x3 = t8[(size_t)c3 * 32 + lane];
        float2 a0 = __half22float2(*(__half2*)&x0.x), b0 = __half22float2(*(__half2*)&x0.y);
        float2 a1 = __half22float2(*(__half2*)&x1.x), b1 = __half22float2(*(__half2*)&x1.y);
        float2 a2 = __half22float2(*(__half2*)&x2.x), b2 = __half22float2(*(__half2*)&x2.y);
        float2 a3 = __half22float2(*(__half2*)&x3.x), b3 = __half22float2(*(__half2*)&x3.y);
        acc.x += w0 * a0.x + w1 * a1.x + w2 * a2.x + w3 * a3.x;
        acc.y += w0 * a0.y + w1 * a1.y + w2 * a2.y + w3 * a3.y;
        acc.z += w0 * b0.x + w1 * b1.x + w2 * b2.x + w3 * b3.x;
        acc.w += w0 * b0.y + w1 * b1.y + w2 * b2.y + w3 * b3.y;
    }
    for (; j < end; ++j) {
        int c = g_colidx[j];
        float w = g_dinv[c] * dv;
        uint2 xx = t8[(size_t)c * 32 + lane];
        float2 a = __half22float2(*(__half2*)&xx.x);
        float2 b = __half22float2(*(__half2*)&xx.y);
        acc.x += w * a.x; acc.y += w * a.y; acc.z += w * b.x; acc.w += w * b.y;
    }

    float4 b  = *(const float4*)(bias  + lane * 4);
    float4 gm = *(const float4*)(gamma + lane * 4);
    float4 bt = *(const float4*)(beta  + lane * 4);
    float4 m  = *(const float4*)(rm    + lane * 4);
    float4 vv = *(const float4*)(rv    + lane * 4);

    float s0 = gm.x * rsqrtf(vv.x + BN_EPS);
    float s1 = gm.y * rsqrtf(vv.y + BN_EPS);
    float s2 = gm.z * rsqrtf(vv.z + BN_EPS);
    float s3 = gm.w * rsqrtf(vv.w + BN_EPS);

    float4 o;
    o.x = fmaxf((acc.x + b.x - m.x) * s0 + bt.x, 0.f);
    o.y = fmaxf((acc.y + b.y - m.y) * s1 + bt.y, 0.f);
    o.z = fmaxf((acc.z + b.z - m.z) * s2 + bt.z, 0.f);
    o.w = fmaxf((acc.w + b.w - m.w) * s3 + bt.w, 0.f);
    ((float4*)g_h)[(size_t)v * 32 + lane] = o;
}

// ---------------- pool + LSTM + FC (block per graph) ----------------
__device__ __forceinline__ float sigmoidf_(float x) { return 1.f / (1.f + expf(-x)); }

__global__ void pool_lstm_kernel(const float* __restrict__ W_ih, const float* __restrict__ b_ih,
                                 const float* __restrict__ b_hh, const float* __restrict__ W_fc,
                                 const float* __restrict__ b_fc, float* __restrict__ out) {
    int g = blockIdx.x;
    int j = threadIdx.x;  // 0..127
    __shared__ __align__(16) float p[HH];
    __shared__ __align__(16) float hn[HH];

    int s = g_gstart[g], e = g_gstart[g + 1];
    float sum = 0.f;
    int n = s;
    for (; n + 3 < e; n += 4) {
        sum += g_h[(size_t)n * HH + j] + g_h[(size_t)(n + 1) * HH + j]
             + g_h[(size_t)(n + 2) * HH + j] + g_h[(size_t)(n + 3) * HH + j];
    }
    for (; n < e; ++n) sum += g_h[(size_t)n * HH + j];
    float cnt = (float)((e - s) > 0 ? (e - s) : 1);
    p[j] = sum / cnt;
    __syncthreads();

    float gate[4];
#pragma unroll
    for (int q = 0; q < 4; q++) {
        const float4* wr = (const float4*)(W_ih + (size_t)(q * HH + j) * HH);
        const float4* pp = (const float4*)p;
        float a = 0.f;
#pragma unroll
        for (int k = 0; k < 32; k++) {
            float4 w = wr[k];
            float4 x = pp[k];
            a += w.x * x.x + w.y * x.y + w.z * x.z + w.w * x.w;
        }
        gate[q] = a + b_ih[q * HH + j] + b_hh[q * HH + j];
    }
    float iv = sigmoidf_(gate[0]);
    float gv = tanhf(gate[2]);
    float ov = sigmoidf_(gate[3]);
    float c = iv * gv;
    hn[j] = ov * tanhf(c);
    __syncthreads();

    if (j < 16) {
        const float4* wr = (const float4*)(W_fc + (size_t)j * HH);
        const float4* hh = (const float4*)hn;
        float a = b_fc[j];
#pragma unroll
        for (int k = 0; k < 32; k++) {
            float4 w = wr[k];
            float4 x = hh[k];
            a += w.x * x.x + w.y * x.y + w.z * x.z + w.w * x.w;
        }
        out[g * 16 + j] = a;
    }
}

// ---------------- host-side symbol address helpers ----------------
static float* get_h_ptr() {
    static float* p = nullptr;
    if (!p) cudaGetSymbolAddress((void**)&p, g_h);
    return p;
}
static __half2* get_t_ptr() {
    static __half2* p = nullptr;
    if (!p) cudaGetSymbolAddress((void**)&p, g_t);
    return p;
}

// ---------------- launch ----------------
extern "C" void kernel_launch(void* const* d_in, const int* in_sizes, int n_in,
                              void* d_out, int out_size) {
    const float* x     = (const float*)d_in[0];
    const int*   eidx  = (const int*)d_in[1];      // [2, E] : src row then dst row
    const int*   batch = (const int*)d_in[2];
    const float* Ws    = (const float*)d_in[3];    // [3,128,128]
    const float* bs    = (const float*)d_in[4];    // [3,128]
    const float* gam   = (const float*)d_in[5];
    const float* bet   = (const float*)d_in[6];
    const float* rms   = (const float*)d_in[7];
    const float* rvs   = (const float*)d_in[8];
    const float* W_ih  = (const float*)d_in[9];    // [512,128]
    // d_in[10] = W_hh (unused: h0 = c0 = 0)
    const float* b_ih  = (const float*)d_in[11];
    const float* b_hh  = (const float*)d_in[12];
    const float* W_fc  = (const float*)d_in[13];   // [16,128]
    const float* b_fc  = (const float*)d_in[14];
    float* out = (float*)d_out;

    const int* src = eidx;
    const int* dst = eidx + EE;

    float*   h_ptr = get_h_ptr();
    __half2* t_ptr = get_t_ptr();

    // side stream + fork/join events (created once, on the uncaptured correctness call)
    static cudaStream_t s2 = nullptr;
    static cudaEvent_t ev_fork = nullptr, ev_join = nullptr;
    if (!s2) {
        cudaStreamCreateWithFlags(&s2, cudaStreamNonBlocking);
        cudaEventCreateWithFlags(&ev_fork, cudaEventDisableTiming);
        cudaEventCreateWithFlags(&ev_join, cudaEventDisableTiming);
    }

    // fork: CSR build chain on s2, GEMM layer 0 on main stream
    cudaEventRecord(ev_fork, 0);
    cudaStreamWaitEvent(s2, ev_fork, 0);

    init_kernel<<<(NN + 255) / 256, 256, 0, s2>>>();
    count_kernel<<<(EE + 255) / 256, 256, 0, s2>>>(dst);
    dinv_kernel<<<(NN + 255) / 256, 256, 0, s2>>>();
    scan_reduce_kernel<<<SCAN_BLOCKS, SCAN_CHUNK, 0, s2>>>();
    scan_spine_kernel<<<1, 128, 0, s2>>>();
    scan_apply_kernel<<<SCAN_BLOCKS, SCAN_CHUNK, 0, s2>>>();
    scatter_kernel<<<(EE + 255) / 256, 256, 0, s2>>>(src, dst);
    bounds_kernel<<<1, 256, 0, s2>>>(batch);
    cudaEventRecord(ev_join, s2);

    int gemm_blocks = (NN + 127) / 128;
    int spmm_blocks = (NN * 32 + 255) / 256;

    gemm_kernel<<<gemm_blocks, 256>>>(x, Ws, t_ptr, NN);          // layer 0 GEMM (independent)
    cudaStreamWaitEvent(0, ev_join, 0);                            // join CSR build
    spmm_kernel<<<spmm_blocks, 256>>>(bs, gam, bet, rms, rvs);

    for (int l = 1; l < LL; l++) {
        gemm_kernel<<<gemm_blocks, 256>>>(h_ptr, Ws + (size_t)l * HH * HH, t_ptr, NN);
        spmm_kernel<<<spmm_blocks, 256>>>(bs + l * HH, gam + l * HH, bet + l * HH,
                                          rms + l * HH, rvs + l * HH);
    }
    pool_lstm_kernel<<<GG, 128>>>(W_ih, b_ih, b_hh, W_fc, b_fc, out);
}

// round 5
// speedup vs baseline: 1.7942x; 1.4512x over previous
#include <cuda_runtime.h>
#include <cuda_fp16.h>
#include <math.h>

#define NN 100000
#define EE 1600000
#define HH 128
#define GG 128
#define LL 3
#define BN_EPS 1e-5f

#define SCAN_CHUNK 1024
#define SCAN_BLOCKS ((NN + SCAN_CHUNK - 1) / SCAN_CHUNK)   // 98

#define APAD 136                       // padded row length in halves (conflict-free)
#define GEMM_SMEM (2 * 128 * APAD * 2) // 69632 bytes

// ---------------- scratch (device globals; no allocation) ----------------
__device__ int   g_deg[NN];
__device__ int   g_fill[NN];
__device__ int   g_rowptr[NN + 1];
__device__ int   g_colidx[EE];
__device__ int   g_gstart[GG + 1];
__device__ int   g_bsum[SCAN_BLOCKS];
__device__ float g_dinv[NN];
__device__ __half2 g_x16[(size_t)NN * HH / 2];  // fp16 input features
__device__ __half2 g_t[(size_t)NN * HH / 2];    // post-GEMM features (fp16)
__device__ __half2 g_h16[(size_t)NN * HH / 2];  // post-SpMM activations (fp16)
__device__ __half  g_w16t[(size_t)LL * HH * HH]; // W transposed [l][n][k] fp16

// ---------------- CSR build ----------------
__global__ void init_kernel() {
    int i = blockIdx.x * blockDim.x + threadIdx.x;
    if (i < NN) { g_deg[i] = 1; g_fill[i] = 0; }   // self-loop counts 1
}

__global__ void count_kernel(const int* __restrict__ dst) {
    int e = blockIdx.x * blockDim.x + threadIdx.x;
    if (e < EE) atomicAdd(&g_deg[dst[e]], 1);
}

__global__ void dinv_kernel() {
    int i = blockIdx.x * blockDim.x + threadIdx.x;
    if (i < NN) g_dinv[i] = rsqrtf((float)g_deg[i]);
}

__device__ __forceinline__ int warp_incl_scan(int v, unsigned lane) {
#pragma unroll
    for (int o = 1; o < 32; o <<= 1) {
        int t = __shfl_up_sync(0xffffffffu, v, o);
        if (lane >= o) v += t;
    }
    return v;
}

__global__ void scan_reduce_kernel() {
    __shared__ int wsum[32];
    int tid = threadIdx.x;
    unsigned lane = tid & 31;
    int wid = tid >> 5;
    int i = blockIdx.x * SCAN_CHUNK + tid;
    int v = (i < NN) ? (g_deg[i] - 1) : 0;
#pragma unroll
    for (int o = 16; o > 0; o >>= 1) v += __shfl_down_sync(0xffffffffu, v, o);
    if (lane == 0) wsum[wid] = v;
    __syncthreads();
    if (wid == 0) {
        int w = wsum[lane];
#pragma unroll
        for (int o = 16; o > 0; o >>= 1) w += __shfl_down_sync(0xffffffffu, w, o);
        if (lane == 0) g_bsum[blockIdx.x] = w;
    }
}

__global__ void scan_spine_kernel() {
    __shared__ int wtot[4];
    int tid = threadIdx.x;              // 0..127
    unsigned lane = tid & 31;
    int wid = tid >> 5;
    int v = (tid < SCAN_BLOCKS) ? g_bsum[tid] : 0;
    int incl = warp_incl_scan(v, lane);
    if (lane == 31) wtot[wid] = incl;
    __syncthreads();
    int off = 0;
    for (int w = 0; w < wid; w++) off += wtot[w];
    if (tid < SCAN_BLOCKS) g_bsum[tid] = off + incl - v;   // exclusive
    if (tid == 127) g_rowptr[NN] = off + incl;             // grand total
}

__global__ void scan_apply_kernel() {
    __shared__ int wsum[32];
    int tid = threadIdx.x;
    unsigned lane = tid & 31;
    int wid = tid >> 5;
    int i = blockIdx.x * SCAN_CHUNK + tid;
    int v = (i < NN) ? (g_deg[i] - 1) : 0;
    int incl = warp_incl_scan(v, lane);
    if (lane == 31) wsum[wid] = incl;
    __syncthreads();
    int woff = 0;
    for (int w = 0; w < wid; w++) woff += wsum[w];
    if (i < NN) g_rowptr[i] = g_bsum[blockIdx.x] + woff + incl - v;
}

__global__ void scatter_kernel(const int* __restrict__ src, const int* __restrict__ dst) {
    int e = blockIdx.x * blockDim.x + threadIdx.x;
    if (e < EE) {
        int d = dst[e];
        int p = g_rowptr[d] + atomicAdd(&g_fill[d], 1);
        g_colidx[p] = src[e];
    }
}

__global__ void bounds_kernel(const int* __restrict__ batch) {
    int g = blockIdx.x * blockDim.x + threadIdx.x;
    if (g > GG) return;
    int lo = 0, hi = NN;
    while (lo < hi) {
        int m = (lo + hi) >> 1;
        if (batch[m] < g) lo = m + 1; else hi = m;
    }
    g_gstart[g] = lo;
}

// ---------------- conversions ----------------
__global__ void convert_x_kernel(const float* __restrict__ x) {
    int i = blockIdx.x * blockDim.x + threadIdx.x;
    if (i < NN * HH / 2) {
        float2 f = ((const float2*)x)[i];
        g_x16[i] = __floats2half2_rn(f.x, f.y);
    }
}

__global__ void convert_w_kernel(const float* __restrict__ Ws) {
    int i = blockIdx.x * blockDim.x + threadIdx.x;   // 0..HH*HH-1
    int l = blockIdx.y;
    if (i < HH * HH) {
        int k = i >> 7, n = i & 127;
        g_w16t[(size_t)l * HH * HH + n * HH + k] = __float2half(Ws[(size_t)l * HH * HH + i]);
    }
}

// ---------------- tensor-core GEMM: C[n,128](fp16) = A[n,128](fp16) @ W ----------------
// block tile 128x128, K=128 fully in smem, 8 warps (4 m x 2 n), mma.m16n8k16.
extern __shared__ __align__(16) char gemm_smem[];

__global__ void __launch_bounds__(256)
gemm_mma_kernel(const __half* __restrict__ A, const __half* __restrict__ Wt,
                __half2* __restrict__ C2, int n) {
    __half* As = (__half*)gemm_smem;                       // [128][APAD]
    __half* Bs = (__half*)(gemm_smem + 128 * APAD * 2);    // [128][APAD] (Wt: [n][k])

    int tid = threadIdx.x;
    int r0 = blockIdx.x * 128;

    // cooperative load A tile (zero-fill OOB rows) and Wt
    const uint4* Ag = (const uint4*)A;
    const uint4* Wg = (const uint4*)Wt;
    uint4* As4 = (uint4*)As;
    uint4* Bs4 = (uint4*)Bs;
#pragma unroll
    for (int i = 0; i < 8; i++) {
        int lin = tid + i * 256;          // 0..2047
        int row = lin >> 4, c = lin & 15; // 16 uint4 per 128-half row
        uint4 v = make_uint4(0, 0, 0, 0);
        if (r0 + row < n) v = Ag[(size_t)(r0 + row) * 16 + c];
        As4[row * 17 + c] = v;            // 17 uint4 = 136 halves (padded)
        Bs4[row * 17 + c] = Wg[row * 16 + c];
    }
    __syncthreads();

    int lane = tid & 31, warp = tid >> 5;
    int wm = (warp & 3) * 32;   // warp row base
    int wn = (warp >> 2) * 64;  // warp col base
    int g = lane >> 2, tg = lane & 3;

    float c[2][8][4];
#pragma unroll
    for (int mt = 0; mt < 2; mt++)
#pragma unroll
        for (int nt = 0; nt < 8; nt++)
#pragma unroll
            for (int q = 0; q < 4; q++) c[mt][nt][q] = 0.f;

#pragma unroll
    for (int ks = 0; ks < 8; ks++) {
        int k0 = ks * 16;
        unsigned a[2][4];
#pragma unroll
        for (int mt = 0; mt < 2; mt++) {
            int rb = wm + mt * 16;
            const __half* p0 = As + (rb + g) * APAD + k0 + tg * 2;
            const __half* p1 = As + (rb + g + 8) * APAD + k0 + tg * 2;
            a[mt][0] = *(const unsigned*)p0;
            a[mt][1] = *(const unsigned*)p1;
            a[mt][2] = *(const unsigned*)(p0 + 8);
            a[mt][3] = *(const unsigned*)(p1 + 8);
        }
#pragma unroll
        for (int nt = 0; nt < 8; nt++) {
            int nrow = wn + nt * 8 + g;
            const __half* q = Bs + nrow * APAD + k0 + tg * 2;
            unsigned b0 = *(const unsigned*)q;
            unsigned b1 = *(const unsigned*)(q + 8);
#pragma unroll
            for (int mt = 0; mt < 2; mt++) {
                asm volatile(
                    "mma.sync.aligned.m16n8k16.row.col.f32.f16.f16.f32 "
                    "{%0,%1,%2,%3}, {%4,%5,%6,%7}, {%8,%9}, {%0,%1,%2,%3};"
                    : "+f"(c[mt][nt][0]), "+f"(c[mt][nt][1]),
                      "+f"(c[mt][nt][2]), "+f"(c[mt][nt][3])
                    : "r"(a[mt][0]), "r"(a[mt][1]), "r"(a[mt][2]), "r"(a[mt][3]),
                      "r"(b0), "r"(b1));
            }
        }
    }

    // epilogue: fp32 -> fp16 pairs, direct 32-bit stores
#pragma unroll
    for (int mt = 0; mt < 2; mt++) {
        int rb = r0 + wm + mt * 16;
#pragma unroll
        for (int nt = 0; nt < 8; nt++) {
            int col2 = ((wn + nt * 8) >> 1) + tg;   // half2 index (64 per row)
            int r_lo = rb + g, r_hi = rb + g + 8;
            if (r_lo < n) C2[(size_t)r_lo * 64 + col2] = __floats2half2_rn(c[mt][nt][0], c[mt][nt][1]);
            if (r_hi < n) C2[(size_t)r_hi * 64 + col2] = __floats2half2_rn(c[mt][nt][2], c[mt][nt][3]);
        }
    }
}

// ---------------- SpMM + bias + BN + ReLU (warp per node, fp16 in/out) ----------------
__global__ void spmm_kernel(const float* __restrict__ bias, const float* __restrict__ gamma,
                            const float* __restrict__ beta, const float* __restrict__ rm,
                            const float* __restrict__ rv) {
    int warp = (blockIdx.x * blockDim.x + threadIdx.x) >> 5;
    if (warp >= NN) return;
    int lane = threadIdx.x & 31;
    int v = warp;
    float dv = g_dinv[v];
    const uint2* t8 = (const uint2*)g_t;   // 8 bytes = 4 fp16 features

    uint2 xs = t8[(size_t)v * 32 + lane];
    float2 f01 = __half22float2(*(__half2*)&xs.x);
    float2 f23 = __half22float2(*(__half2*)&xs.y);
    float ws = dv * dv;
    float4 acc = make_float4(ws * f01.x, ws * f01.y, ws * f23.x, ws * f23.y);

    int j = g_rowptr[v], end = g_rowptr[v + 1];
    for (; j + 3 < end; j += 4) {
        int c0 = g_colidx[j], c1 = g_colidx[j + 1], c2 = g_colidx[j + 2], c3 = g_colidx[j + 3];
        float w0 = g_dinv[c0] * dv, w1 = g_dinv[c1] * dv, w2 = g_dinv[c2] * dv, w3 = g_dinv[c3] * dv;
        uint2 x0 = t8[(size_t)c0 * 32 + lane];
        uint2 x1 = t8[(size_t)c1 * 32 + lane];
        uint2 x2 = t8[(size_t)c2 * 32 + lane];
        uint2 x3 = t8[(size_t)c3 * 32 + lane];
        float2 a0 = __half22float2(*(__half2*)&x0.x), b0 = __half22float2(*(__half2*)&x0.y);
        float2 a1 = __half22float2(*(__half2*)&x1.x), b1 = __half22float2(*(__half2*)&x1.y);
        float2 a2 = __half22float2(*(__half2*)&x2.x), b2 = __half22float2(*(__half2*)&x2.y);
        float2 a3 = __half22float2(*(__half2*)&x3.x), b3 = __half22float2(*(__half2*)&x3.y);
        acc.x += w0 * a0.x + w1 * a1.x + w2 * a2.x + w3 * a3.x;
        acc.y += w0 * a0.y + w1 * a1.y + w2 * a2.y + w3 * a3.y;
        acc.z += w0 * b0.x + w1 * b1.x + w2 * b2.x + w3 * b3.x;
        acc.w += w0 * b0.y + w1 * b1.y + w2 * b2.y + w3 * b3.y;
    }
    for (; j < end; ++j) {
        int cc = g_colidx[j];
        float w = g_dinv[cc] * dv;
        uint2 xx = t8[(size_t)cc * 32 + lane];
        float2 a = __half22float2(*(__half2*)&xx.x);
        float2 b = __half22float2(*(__half2*)&xx.y);
        acc.x += w * a.x; acc.y += w * a.y; acc.z += w * b.x; acc.w += w * b.y;
    }

    float4 b  = *(const float4*)(bias  + lane * 4);
    float4 gm = *(const float4*)(gamma + lane * 4);
    float4 bt = *(const float4*)(beta  + lane * 4);
    float4 m  = *(const float4*)(rm    + lane * 4);
    float4 vv = *(const float4*)(rv    + lane * 4);

    float s0 = gm.x * rsqrtf(vv.x + BN_EPS);
    float s1 = gm.y * rsqrtf(vv.y + BN_EPS);
    float s2 = gm.z * rsqrtf(vv.z + BN_EPS);
    float s3 = gm.w * rsqrtf(vv.w + BN_EPS);

    float o0 = fmaxf((acc.x + b.x - m.x) * s0 + bt.x, 0.f);
    float o1 = fmaxf((acc.y + b.y - m.y) * s1 + bt.y, 0.f);
    float o2 = fmaxf((acc.z + b.z - m.z) * s2 + bt.z, 0.f);
    float o3 = fmaxf((acc.w + b.w - m.w) * s3 + bt.w, 0.f);

    __half2 p0 = __floats2half2_rn(o0, o1);
    __half2 p1 = __floats2half2_rn(o2, o3);
    uint2 u; u.x = *(unsigned*)&p0; u.y = *(unsigned*)&p1;
    ((uint2*)g_h16)[(size_t)v * 32 + lane] = u;
}

// ---------------- pool + LSTM + FC (block per graph) ----------------
__device__ __forceinline__ float sigmoidf_(float x) { return 1.f / (1.f + expf(-x)); }

__global__ void pool_lstm_kernel(const float* __restrict__ W_ih, const float* __restrict__ b_ih,
                                 const float* __restrict__ b_hh, const float* __restrict__ W_fc,
                                 const float* __restrict__ b_fc, float* __restrict__ out) {
    int g = blockIdx.x;
    int j = threadIdx.x;  // 0..127
    __shared__ __align__(16) float p[HH];
    __shared__ __align__(16) float hn[HH];

    const __half* hb = (const __half*)g_h16;
    int s = g_gstart[g], e = g_gstart[g + 1];
    float sum = 0.f;
    int n = s;
    for (; n + 3 < e; n += 4) {
        sum += __half2float(hb[(size_t)n * HH + j]) + __half2float(hb[(size_t)(n + 1) * HH + j])
             + __half2float(hb[(size_t)(n + 2) * HH + j]) + __half2float(hb[(size_t)(n + 3) * HH + j]);
    }
    for (; n < e; ++n) sum += __half2float(hb[(size_t)n * HH + j]);
    float cnt = (float)((e - s) > 0 ? (e - s) : 1);
    p[j] = sum / cnt;
    __syncthreads();

    float gate[4];
#pragma unroll
    for (int q = 0; q < 4; q++) {
        const float4* wr = (const float4*)(W_ih + (size_t)(q * HH + j) * HH);
        const float4* pp = (const float4*)p;
        float a = 0.f;
#pragma unroll
        for (int k = 0; k < 32; k++) {
            float4 w = wr[k];
            float4 x = pp[k];
            a += w.x * x.x + w.y * x.y + w.z * x.z + w.w * x.w;
        }
        gate[q] = a + b_ih[q * HH + j] + b_hh[q * HH + j];
    }
    float iv = sigmoidf_(gate[0]);
    float gv = tanhf(gate[2]);
    float ov = sigmoidf_(gate[3]);
    float c = iv * gv;
    hn[j] = ov * tanhf(c);
    __syncthreads();

    if (j < 16) {
        const float4* wr = (const float4*)(W_fc + (size_t)j * HH);
        const float4* hh = (const float4*)hn;
        float a = b_fc[j];
#pragma unroll
        for (int k = 0; k < 32; k++) {
            float4 w = wr[k];
            float4 x = hh[k];
            a += w.x * x.x + w.y * x.y + w.z * x.z + w.w * x.w;
        }
        out[g * 16 + j] = a;
    }
}

// ---------------- host-side symbol address helpers ----------------
static __half* get_x16_ptr() {
    static __half* p = nullptr;
    if (!p) cudaGetSymbolAddress((void**)&p, g_x16);
    return p;
}
static __half* get_h16_ptr() {
    static __half* p = nullptr;
    if (!p) cudaGetSymbolAddress((void**)&p, g_h16);
    return p;
}
static __half2* get_t_ptr() {
    static __half2* p = nullptr;
    if (!p) cudaGetSymbolAddress((void**)&p, g_t);
    return p;
}
static __half* get_w16t_ptr() {
    static __half* p = nullptr;
    if (!p) cudaGetSymbolAddress((void**)&p, g_w16t);
    return p;
}

// ---------------- launch ----------------
extern "C" void kernel_launch(void* const* d_in, const int* in_sizes, int n_in,
                              void* d_out, int out_size) {
    const float* x     = (const float*)d_in[0];
    const int*   eidx  = (const int*)d_in[1];      // [2, E]
    const int*   batch = (const int*)d_in[2];
    const float* Ws    = (const float*)d_in[3];    // [3,128,128]
    const float* bs    = (const float*)d_in[4];
    const float* gam   = (const float*)d_in[5];
    const float* bet   = (const float*)d_in[6];
    const float* rms   = (const float*)d_in[7];
    const float* rvs   = (const float*)d_in[8];
    const float* W_ih  = (const float*)d_in[9];
    // d_in[10] = W_hh (unused: h0 = c0 = 0)
    const float* b_ih  = (const float*)d_in[11];
    const float* b_hh  = (const float*)d_in[12];
    const float* W_fc  = (const float*)d_in[13];
    const float* b_fc  = (const float*)d_in[14];
    float* out = (float*)d_out;

    const int* src = eidx;
    const int* dst = eidx + EE;

    __half*  x16   = get_x16_ptr();
    __half*  h16   = get_h16_ptr();
    __half2* t_ptr = get_t_ptr();
    __half*  w16t  = get_w16t_ptr();

    static cudaStream_t s2 = nullptr;
    static cudaEvent_t ev_fork = nullptr, ev_join = nullptr;
    if (!s2) {
        cudaStreamCreateWithFlags(&s2, cudaStreamNonBlocking);
        cudaEventCreateWithFlags(&ev_fork, cudaEventDisableTiming);
        cudaEventCreateWithFlags(&ev_join, cudaEventDisableTiming);
        cudaFuncSetAttribute(gemm_mma_kernel,
                             cudaFuncAttributeMaxDynamicSharedMemorySize, GEMM_SMEM);
    }

    // fork: CSR build chain on s2
    cudaEventRecord(ev_fork, 0);
    cudaStreamWaitEvent(s2, ev_fork, 0);

    init_kernel<<<(NN + 255) / 256, 256, 0, s2>>>();
    count_kernel<<<(EE + 255) / 256, 256, 0, s2>>>(dst);
    dinv_kernel<<<(NN + 255) / 256, 256, 0, s2>>>();
    scan_reduce_kernel<<<SCAN_BLOCKS, SCAN_CHUNK, 0, s2>>>();
    scan_spine_kernel<<<1, 128, 0, s2>>>();
    scan_apply_kernel<<<SCAN_BLOCKS, SCAN_CHUNK, 0, s2>>>();
    scatter_kernel<<<(EE + 255) / 256, 256, 0, s2>>>(src, dst);
    bounds_kernel<<<1, 256, 0, s2>>>(batch);
    cudaEventRecord(ev_join, s2);

    // main stream: conversions + layer pipeline
    {
        dim3 wgrid((HH * HH + 255) / 256, LL);
        convert_w_kernel<<<wgrid, 256>>>(Ws);
    }
    convert_x_kernel<<<(NN * HH / 2 + 255) / 256, 256>>>(x);

    int gemm_blocks = (NN + 127) / 128;
    int spmm_blocks = (NN * 32 + 255) / 256;

    gemm_mma_kernel<<<gemm_blocks, 256, GEMM_SMEM>>>(x16, w16t, t_ptr, NN);
    cudaStreamWaitEvent(0, ev_join, 0);                       // join CSR build
    spmm_kernel<<<spmm_blocks, 256>>>(bs, gam, bet, rms, rvs);

    for (int l = 1; l < LL; l++) {
        gemm_mma_kernel<<<gemm_blocks, 256, GEMM_SMEM>>>(h16, w16t + (size_t)l * HH * HH,
                                                         t_ptr, NN);
        spmm_kernel<<<spmm_blocks, 256>>>(bs + l * HH, gam + l * HH, bet + l * HH,
                                          rms + l * HH, rvs + l * HH);
    }
    pool_lstm_kernel<<<GG, 128>>>(W_ih, b_ih, b_hh, W_fc, b_fc, out);
}